// round 2
// baseline (speedup 1.0000x reference)
#include <cuda_runtime.h>

// Problem constants
#define BQ   2
#define TT   1024
#define DD   1024
#define HH   16
#define DHD  64
#define KVL  3072
#define MEML 1024
#define CMEML 1024
#define SCALE_F 0.125f

// ---------------- scratch (device globals; no allocation) ----------------
__device__ float g_kv_in [(long)BQ * KVL * DD];        //  6,291,456
__device__ float g_q     [(long)BQ * TT  * DD];        //  2,097,152
__device__ float g_kv_out[(long)BQ * KVL * 2 * DD];    // 12,582,912
__device__ float g_dots  [(long)BQ * HH * TT * KVL];   // 100,663,296
__device__ float g_ctx   [(long)BQ * TT  * DD];        //  2,097,152
__device__ float g_wt    [4096L * 1024];               //  4,194,304

// ---------------- kv concat: [cmem, mem, x] -> g_kv_in -------------------
__global__ void concat_kv_kernel(const float* __restrict__ x,
                                 const float* __restrict__ mem,
                                 const float* __restrict__ cmem) {
    long i4 = (long)blockIdx.x * blockDim.x + threadIdx.x;
    const long total4 = (long)BQ * KVL * DD / 4;
    if (i4 >= total4) return;
    long e = i4 * 4;
    int  b   = (int)(e / ((long)KVL * DD));
    long rem = e - (long)b * KVL * DD;
    int  t   = (int)(rem / DD);
    int  c   = (int)(rem - (long)t * DD);
    const float* src;
    if (t < CMEML)              src = cmem + (long)b * CMEML * DD + (long)t * DD + c;
    else if (t < CMEML + MEML)  src = mem  + (long)b * MEML  * DD + (long)(t - CMEML) * DD + c;
    else                        src = x    + (long)b * TT    * DD + (long)(t - CMEML - MEML) * DD + c;
    *(float4*)(g_kv_in + e) = *(const float4*)src;
}

// ---------------- generic SGEMM: C = A(MxK) @ B(KxN) (+bias) -------------
// 128x128 tile, K-step 8, 256 threads, 8x8 per thread. All dims must divide.
__global__ void sgemm_kernel(const float* __restrict__ A, const float* __restrict__ B,
                             const float* __restrict__ bias, float* __restrict__ C,
                             int M, int N, int K, long sA, long sB, long sC) {
    A += (long)blockIdx.z * sA;
    B += (long)blockIdx.z * sB;
    C += (long)blockIdx.z * sC;
    __shared__ __align__(16) float As[8][128];
    __shared__ __align__(16) float Bs[8][128];
    int tid = threadIdx.x;
    int m0 = blockIdx.y << 7, n0 = blockIdx.x << 7;
    int tx = tid & 15, ty = tid >> 4;
    float acc[8][8] = {};
    int ar = tid >> 1, ac = (tid & 1) << 2;
    int br = tid >> 5, bc = (tid & 31) << 2;
    for (int k0 = 0; k0 < K; k0 += 8) {
        float4 av = *(const float4*)(A + (long)(m0 + ar) * K + k0 + ac);
        float4 bv = *(const float4*)(B + (long)(k0 + br) * N + n0 + bc);
        As[ac + 0][ar] = av.x; As[ac + 1][ar] = av.y;
        As[ac + 2][ar] = av.z; As[ac + 3][ar] = av.w;
        *(float4*)&Bs[br][bc] = bv;
        __syncthreads();
        #pragma unroll
        for (int kk = 0; kk < 8; kk++) {
            float ra[8], rb[8];
            *(float4*)&ra[0] = *(float4*)&As[kk][ty << 3];
            *(float4*)&ra[4] = *(float4*)&As[kk][(ty << 3) + 4];
            *(float4*)&rb[0] = *(float4*)&Bs[kk][tx << 3];
            *(float4*)&rb[4] = *(float4*)&Bs[kk][(tx << 3) + 4];
            #pragma unroll
            for (int i = 0; i < 8; i++)
                #pragma unroll
                for (int j = 0; j < 8; j++)
                    acc[i][j] += ra[i] * rb[j];
        }
        __syncthreads();
    }
    #pragma unroll
    for (int i = 0; i < 8; i++) {
        int m = m0 + (ty << 3) + i;
        #pragma unroll
        for (int j = 0; j < 8; j += 4) {
            int n = n0 + (tx << 3) + j;
            float4 v = make_float4(acc[i][j], acc[i][j + 1], acc[i][j + 2], acc[i][j + 3]);
            if (bias) { v.x += bias[n]; v.y += bias[n + 1]; v.z += bias[n + 2]; v.w += bias[n + 3]; }
            *(float4*)(C + (long)m * N + n) = v;
        }
    }
}

// ---------------- fused QK^T + shifted positional dots -------------------
// dots[b,h,i,j] = SCALE * ( q.k + (jj<3072 ? q.pos_emb[h,jj] : 0) ), jj = j+1023-i
// 64x64 output tile. pos rows form a 127-wide diagonal band -> streamed
// through the K smem buffer in two 64-row halves.
__global__ void dots_kernel(const float* __restrict__ pos) {
    int bh = blockIdx.z; int b = bh >> 4; int h = bh & 15;
    int i0 = blockIdx.y << 6;
    int j0 = blockIdx.x << 6;
    __shared__ __align__(16) float Qs[64][68];
    __shared__ __align__(16) float Ks[64][68];
    int tid = threadIdx.x;
    int tx = tid & 15, ty = tid >> 4;
    {
        int r = tid >> 2; int c0 = (tid & 3) << 4;
        const float* qs = g_q      + ((long)(b * TT  + i0 + r)) * DD       + h * DHD + c0;
        const float* ks = g_kv_out + ((long)(b * KVL + j0 + r)) * (2 * DD) + h * DHD + c0;
        #pragma unroll
        for (int u = 0; u < 4; u++) {
            *(float4*)&Qs[r][c0 + 4 * u] = *(const float4*)(qs + 4 * u);
            *(float4*)&Ks[r][c0 + 4 * u] = *(const float4*)(ks + 4 * u);
        }
    }
    __syncthreads();
    float acc[4][4] = {};
    #pragma unroll
    for (int d4 = 0; d4 < 16; d4++) {
        float4 rq[4], rk[4];
        #pragma unroll
        for (int r = 0; r < 4; r++) rq[r] = *(float4*)&Qs[ty * 4 + r][d4 * 4];
        #pragma unroll
        for (int c = 0; c < 4; c++) rk[c] = *(float4*)&Ks[tx * 4 + c][d4 * 4];
        #pragma unroll
        for (int r = 0; r < 4; r++)
            #pragma unroll
            for (int c = 0; c < 4; c++)
                acc[r][c] += rq[r].x * rk[c].x + rq[r].y * rk[c].y
                           + rq[r].z * rk[c].z + rq[r].w * rk[c].w;
    }
    // positional band: jj = j0-i0+1023 + lj - li, local prow = lj - li + 63 in [0,126]
    int jjmin = j0 - i0 + 960;   // >= 0 always (i0 <= 960)
    #pragma unroll
    for (int half = 0; half < 2; half++) {
        __syncthreads();
        {
            int r = tid >> 2; int c0 = (tid & 3) << 4;
            int jj = jjmin + half * 64 + r;
            if (jj < KVL) {
                const float* ps = pos + ((long)h * KVL + jj) * DHD + c0;
                #pragma unroll
                for (int u = 0; u < 4; u++)
                    *(float4*)&Ks[r][c0 + 4 * u] = *(const float4*)(ps + 4 * u);
            } else {
                float4 z = make_float4(0.f, 0.f, 0.f, 0.f);
                #pragma unroll
                for (int u = 0; u < 4; u++) *(float4*)&Ks[r][c0 + 4 * u] = z;
            }
        }
        __syncthreads();
        #pragma unroll
        for (int d4 = 0; d4 < 16; d4++) {
            float4 rq[4];
            #pragma unroll
            for (int r = 0; r < 4; r++) rq[r] = *(float4*)&Qs[ty * 4 + r][d4 * 4];
            #pragma unroll
            for (int r = 0; r < 4; r++) {
                #pragma unroll
                for (int c = 0; c < 4; c++) {
                    int prow = (tx * 4 + c) + 63 - (ty * 4 + r);
                    if ((prow >> 6) == half) {
                        float4 rp = *(float4*)&Ks[prow & 63][d4 * 4];
                        acc[r][c] += rq[r].x * rp.x + rq[r].y * rp.y
                                   + rq[r].z * rp.z + rq[r].w * rp.w;
                    }
                }
            }
        }
    }
    #pragma unroll
    for (int r = 0; r < 4; r++) {
        long base = ((long)bh * TT + i0 + ty * 4 + r) * KVL + j0 + tx * 4;
        float4 v = make_float4(SCALE_F * acc[r][0], SCALE_F * acc[r][1],
                               SCALE_F * acc[r][2], SCALE_F * acc[r][3]);
        *(float4*)(g_dots + base) = v;
    }
}

// ---------------- softmax over 3072 keys, one block per row --------------
__global__ void softmax_kernel() {
    float* p = g_dots + (long)blockIdx.x * KVL;
    int tid = threadIdx.x;
    __shared__ float red[8], red2[8];
    float v[12];
    float m = -1e30f;
    #pragma unroll
    for (int u = 0; u < 12; u++) { v[u] = p[tid + (u << 8)]; m = fmaxf(m, v[u]); }
    #pragma unroll
    for (int o = 16; o; o >>= 1) m = fmaxf(m, __shfl_xor_sync(0xffffffffu, m, o));
    if ((tid & 31) == 0) red[tid >> 5] = m;
    __syncthreads();
    m = red[0];
    #pragma unroll
    for (int i = 1; i < 8; i++) m = fmaxf(m, red[i]);
    float s = 0.f;
    #pragma unroll
    for (int u = 0; u < 12; u++) { v[u] = __expf(v[u] - m); s += v[u]; }
    #pragma unroll
    for (int o = 16; o; o >>= 1) s += __shfl_xor_sync(0xffffffffu, s, o);
    if ((tid & 31) == 0) red2[tid >> 5] = s;
    __syncthreads();
    s = red2[0] + red2[1] + red2[2] + red2[3] + red2[4] + red2[5] + red2[6] + red2[7];
    float inv = 1.0f / s;
    #pragma unroll
    for (int u = 0; u < 12; u++) p[tid + (u << 8)] = v[u] * inv;
}

// ---------------- attn @ V -> ctx in (B,T,D) layout ----------------------
__global__ void av_kernel() {
    int bh = blockIdx.z; int b = bh >> 4; int h = bh & 15;
    int i0 = blockIdx.y << 6;
    __shared__ __align__(16) float As[64][68];
    __shared__ __align__(16) float Vs[64][68];
    int tid = threadIdx.x;
    int tx = tid & 15, ty = tid >> 4;
    float acc[4][4] = {};
    for (int jc = 0; jc < KVL; jc += 64) {
        __syncthreads();
        {
            int r = tid >> 2; int c0 = (tid & 3) << 4;
            const float* as = g_dots   + ((long)bh * TT + i0 + r) * KVL + jc + c0;
            const float* vs = g_kv_out + ((long)(b * KVL + jc + r)) * (2 * DD) + DD + h * DHD + c0;
            #pragma unroll
            for (int u = 0; u < 4; u++) {
                *(float4*)&As[r][c0 + 4 * u] = *(const float4*)(as + 4 * u);
                *(float4*)&Vs[r][c0 + 4 * u] = *(const float4*)(vs + 4 * u);
            }
        }
        __syncthreads();
        #pragma unroll
        for (int jj = 0; jj < 64; jj++) {
            float ra[4];
            #pragma unroll
            for (int r = 0; r < 4; r++) ra[r] = As[ty * 4 + r][jj];
            float4 rv = *(float4*)&Vs[jj][tx * 4];
            #pragma unroll
            for (int r = 0; r < 4; r++) {
                acc[r][0] += ra[r] * rv.x; acc[r][1] += ra[r] * rv.y;
                acc[r][2] += ra[r] * rv.z; acc[r][3] += ra[r] * rv.w;
            }
        }
    }
    #pragma unroll
    for (int r = 0; r < 4; r++) {
        float4 v = make_float4(acc[r][0], acc[r][1], acc[r][2], acc[r][3]);
        *(float4*)(g_ctx + ((long)(b * TT + i0 + ty * 4 + r)) * DD + h * DHD + tx * 4) = v;
    }
}

// ---------------- conv weight transpose: (O,I,4) -> (r*1024+ci, O) -------
__global__ void wtrans_kernel(const float* __restrict__ w) {
    long idx = (long)blockIdx.x * blockDim.x + threadIdx.x;
    if (idx >= 4096L * 1024) return;
    int k = (int)(idx >> 10);
    int o = (int)(idx & 1023);
    g_wt[idx] = w[(long)o * 4096 + ((k & 1023) << 2) + (k >> 10)];
}

// ---------------- simple vectorized copy + aux ---------------------------
__global__ void copy4_kernel(const float4* __restrict__ src, float4* __restrict__ dst, long n4) {
    long i = (long)blockIdx.x * blockDim.x + threadIdx.x;
    if (i < n4) dst[i] = src[i];
}
__global__ void aux_kernel(float* out) { *out = 0.f; }

// ---------------- launch ---------------------------------------------------
extern "C" void kernel_launch(void* const* d_in, const int* in_sizes, int n_in,
                              void* d_out_, int out_size) {
    const float* x      = (const float*)d_in[0];
    const float* mem    = (const float*)d_in[1];
    const float* cmem   = (const float*)d_in[2];
    const float* pos    = (const float*)d_in[3];
    const float* Wq     = (const float*)d_in[4];
    const float* Wkv    = (const float*)d_in[5];
    const float* Wout   = (const float*)d_in[6];
    const float* b_out  = (const float*)d_in[7];
    const float* conv_w = (const float*)d_in[8];
    const float* conv_b = (const float*)d_in[9];
    float* out = (float*)d_out_;

    float *p_kvin, *p_q, *p_kvout, *p_ctx, *p_wt;
    cudaGetSymbolAddress((void**)&p_kvin,  g_kv_in);
    cudaGetSymbolAddress((void**)&p_q,     g_q);
    cudaGetSymbolAddress((void**)&p_kvout, g_kv_out);
    cudaGetSymbolAddress((void**)&p_ctx,   g_ctx);
    cudaGetSymbolAddress((void**)&p_wt,    g_wt);

    // kv concat and projections
    concat_kv_kernel<<<6144, 256>>>(x, mem, cmem);
    sgemm_kernel<<<dim3(8, 16, 1),  256>>>(x,      Wq,  nullptr, p_q,     2048, 1024, 1024, 0, 0, 0);
    sgemm_kernel<<<dim3(16, 48, 1), 256>>>(p_kvin, Wkv, nullptr, p_kvout, 6144, 2048, 1024, 0, 0, 0);

    // attention
    dots_kernel<<<dim3(48, 16, 32), 256>>>(pos);
    softmax_kernel<<<32768, 256>>>();
    av_kernel<<<dim3(1, 16, 32), 256>>>();

    // output projection -> logits
    sgemm_kernel<<<dim3(8, 16, 1), 256>>>(p_ctx, Wout, b_out, out, 2048, 1024, 1024, 0, 0, 0);

    // new_mem = x
    copy4_kernel<<<2048, 256>>>((const float4*)x, (float4*)(out + 2097152), 524288);

    // new_cmem part 1: cmem[:, 256:] (768 rows per batch)
    copy4_kernel<<<768, 256>>>((const float4*)(cmem + 262144),  (float4*)(out + 4194304), 196608);
    copy4_kernel<<<768, 256>>>((const float4*)(cmem + 1310720), (float4*)(out + 5242880), 196608);

    // new_cmem part 2: strided conv as GEMM (M=256, K=4096, N=1024) per batch
    wtrans_kernel<<<16384, 256>>>(conv_w);
    sgemm_kernel<<<dim3(8, 2, 2), 256>>>(mem, p_wt, conv_b, out + 4980736,
                                         256, 1024, 4096, 1048576, 0, 1048576);

    // aux_loss = 0
    aux_kernel<<<1, 1>>>(out + 6291456);
}

// round 3
// speedup vs baseline: 7.1696x; 7.1696x over previous
#include <cuda_runtime.h>

// Problem constants
#define BQ   2
#define TT   1024
#define DD   1024
#define HH   16
#define DHD  64
#define KVL  3072
#define MEML 1024
#define CMEML 1024
#define SCALE_F 0.125f

// ---------------- scratch (device globals; no allocation) ----------------
__device__ float g_kv_in [(long)BQ * KVL * DD];        //  6,291,456
__device__ float g_q     [(long)BQ * TT  * DD];        //  2,097,152
__device__ float g_kv_out[(long)BQ * KVL * 2 * DD];    // 12,582,912
__device__ float g_dots  [(long)BQ * HH * TT * KVL];   // 100,663,296
__device__ float g_pos   [(long)BQ * HH * TT * KVL];   // 100,663,296
__device__ float g_ctx   [(long)BQ * TT  * DD];        //  2,097,152
__device__ float g_wt    [4096L * 1024];               //  4,194,304

// ---------------- kv concat: [cmem, mem, x] -> g_kv_in -------------------
__global__ void concat_kv_kernel(const float* __restrict__ x,
                                 const float* __restrict__ mem,
                                 const float* __restrict__ cmem) {
    long i4 = (long)blockIdx.x * blockDim.x + threadIdx.x;
    const long total4 = (long)BQ * KVL * DD / 4;
    if (i4 >= total4) return;
    long e = i4 * 4;
    int  b   = (int)(e / ((long)KVL * DD));
    long rem = e - (long)b * KVL * DD;
    int  t   = (int)(rem / DD);
    int  c   = (int)(rem - (long)t * DD);
    const float* src;
    if (t < CMEML)              src = cmem + (long)b * CMEML * DD + (long)t * DD + c;
    else if (t < CMEML + MEML)  src = mem  + (long)b * MEML  * DD + (long)(t - CMEML) * DD + c;
    else                        src = x    + (long)b * TT    * DD + (long)(t - CMEML - MEML) * DD + c;
    *(float4*)(g_kv_in + e) = *(const float4*)src;
}

// ---------------- TF32 tensor-core GEMM --------------------------------
__device__ __forceinline__ unsigned f2tf(float f) {
    unsigned u;
    asm("cvt.rna.tf32.f32 %0, %1;" : "=r"(u) : "f"(f));
    return u;
}

__device__ __forceinline__ void mma_tf32(float c[4], const unsigned a[4], const unsigned b[2]) {
    asm volatile(
        "mma.sync.aligned.m16n8k8.row.col.f32.tf32.tf32.f32 "
        "{%0,%1,%2,%3},{%4,%5,%6,%7},{%8,%9},{%0,%1,%2,%3};"
        : "+f"(c[0]), "+f"(c[1]), "+f"(c[2]), "+f"(c[3])
        : "r"(a[0]), "r"(a[1]), "r"(a[2]), "r"(a[3]), "r"(b[0]), "r"(b[1]));
}

// C[bz] = alpha * A(MxK) @ op(B) + bias.  Row-major everywhere.
// TRANSB=false: B is KxN.  TRANSB=true: B is NxK (C = A @ B^T).
// z -> (zb = z/ZH, zh = z%ZH); per-matrix base offsets zb*s?b + zh*s?h.
// Requires: M % BM == 0, N % BN == 0, K % 16 == 0. 256 threads.
template<int BM, int BN, int WM, int WN, bool TRANSB>
__global__ __launch_bounds__(256) void mma_gemm(
    const float* __restrict__ A, const float* __restrict__ B,
    const float* __restrict__ bias, float* __restrict__ C,
    int K, int lda, int ldb, int ldc, float alpha, int ZH,
    long sAb, long sAh, long sBb, long sBh, long sCb, long sCh)
{
    constexpr int BK = 16;
    int z = blockIdx.z;
    int zb = z / ZH, zh = z - zb * ZH;
    A += (long)zb * sAb + (long)zh * sAh;
    B += (long)zb * sBb + (long)zh * sBh;
    C += (long)zb * sCb + (long)zh * sCh;
    int m0 = blockIdx.y * BM, n0 = blockIdx.x * BN;

    // As: [k-padded row-major m x k], stride 20 words -> conflict-free frag loads
    __shared__ unsigned As[2][BM][20];
    __shared__ unsigned Bs[2][TRANSB ? BN : BK][TRANSB ? 20 : BN + 8];

    int tid  = threadIdx.x;
    int warp = tid >> 5, lane = tid & 31;
    int gid  = lane >> 2, tg = lane & 3;
    constexpr int WNN = BN / WN;
    int wm = warp / WNN, wn = warp % WNN;
    constexpr int MI = WM / 16, NI = WN / 8;

    float acc[MI][NI][4];
    #pragma unroll
    for (int mi = 0; mi < MI; mi++)
        #pragma unroll
        for (int ni = 0; ni < NI; ni++)
            #pragma unroll
            for (int u = 0; u < 4; u++) acc[mi][ni][u] = 0.f;

    auto loadTiles = [&](int k0, int buf) {
        #pragma unroll
        for (int i = 0; i < BM / 64; i++) {
            int f = tid + i * 256;
            int r = f >> 2, c = (f & 3) << 2;
            float4 v = *(const float4*)(A + (long)(m0 + r) * lda + k0 + c);
            As[buf][r][c]     = f2tf(v.x);
            As[buf][r][c + 1] = f2tf(v.y);
            As[buf][r][c + 2] = f2tf(v.z);
            As[buf][r][c + 3] = f2tf(v.w);
        }
        if (TRANSB) {
            #pragma unroll
            for (int i = 0; i < BN / 64; i++) {
                int f = tid + i * 256;
                int r = f >> 2, c = (f & 3) << 2;
                float4 v = *(const float4*)(B + (long)(n0 + r) * ldb + k0 + c);
                Bs[buf][r][c]     = f2tf(v.x);
                Bs[buf][r][c + 1] = f2tf(v.y);
                Bs[buf][r][c + 2] = f2tf(v.z);
                Bs[buf][r][c + 3] = f2tf(v.w);
            }
        } else {
            constexpr int B4 = BN / 4;
            #pragma unroll
            for (int i = 0; i < BN / 64; i++) {
                int f = tid + i * 256;
                int r = f / B4, c = (f % B4) * 4;
                float4 v = *(const float4*)(B + (long)(k0 + r) * ldb + n0 + c);
                Bs[buf][r][c]     = f2tf(v.x);
                Bs[buf][r][c + 1] = f2tf(v.y);
                Bs[buf][r][c + 2] = f2tf(v.z);
                Bs[buf][r][c + 3] = f2tf(v.w);
            }
        }
    };

    loadTiles(0, 0);
    __syncthreads();
    int nk = K / BK;
    for (int kt = 0; kt < nk; kt++) {
        int buf = kt & 1;
        if (kt + 1 < nk) loadTiles((kt + 1) * BK, buf ^ 1);
        #pragma unroll
        for (int ks = 0; ks < 16; ks += 8) {
            unsigned af[MI][4], bf[NI][2];
            #pragma unroll
            for (int mi = 0; mi < MI; mi++) {
                int r = wm * WM + mi * 16;
                af[mi][0] = As[buf][r + gid][ks + tg];
                af[mi][1] = As[buf][r + gid + 8][ks + tg];
                af[mi][2] = As[buf][r + gid][ks + tg + 4];
                af[mi][3] = As[buf][r + gid + 8][ks + tg + 4];
            }
            #pragma unroll
            for (int ni = 0; ni < NI; ni++) {
                int cb = wn * WN + ni * 8;
                if (TRANSB) {
                    bf[ni][0] = Bs[buf][cb + gid][ks + tg];
                    bf[ni][1] = Bs[buf][cb + gid][ks + tg + 4];
                } else {
                    bf[ni][0] = Bs[buf][ks + tg][cb + gid];
                    bf[ni][1] = Bs[buf][ks + tg + 4][cb + gid];
                }
            }
            #pragma unroll
            for (int mi = 0; mi < MI; mi++)
                #pragma unroll
                for (int ni = 0; ni < NI; ni++)
                    mma_tf32(acc[mi][ni], af[mi], bf[ni]);
        }
        __syncthreads();
    }

    #pragma unroll
    for (int mi = 0; mi < MI; mi++) {
        #pragma unroll
        for (int ni = 0; ni < NI; ni++) {
            int r0 = m0 + wm * WM + mi * 16 + gid;
            int c  = n0 + wn * WN + ni * 8 + 2 * tg;
            float b0 = 0.f, b1 = 0.f;
            if (bias) { b0 = bias[c]; b1 = bias[c + 1]; }
            float2 v0 = make_float2(alpha * acc[mi][ni][0] + b0, alpha * acc[mi][ni][1] + b1);
            float2 v1 = make_float2(alpha * acc[mi][ni][2] + b0, alpha * acc[mi][ni][3] + b1);
            *(float2*)(C + (long)r0 * ldc + c)       = v0;
            *(float2*)(C + (long)(r0 + 8) * ldc + c) = v1;
        }
    }
}

// ---------------- softmax (fused shifted positional add) -----------------
// row r = (b*16+h)*1024 + i.
// dots[r][j] += P[r][j + 1023 - i]  when j + 1023 - i < 3072 (always >= 0).
__global__ void softmax_kernel() {
    long row = blockIdx.x;
    int  i   = (int)(row & 1023);
    float* p = g_dots + row * KVL;
    const float* pp = g_pos + row * KVL + (1023 - i);
    int lim = 2049 + i;               // j < lim  <=>  j+1023-i < 3072
    int tid = threadIdx.x;
    __shared__ float red[8], red2[8];
    float v[12];
    float m = -1e30f;
    #pragma unroll
    for (int u = 0; u < 12; u++) {
        int j = tid + (u << 8);
        float d = p[j];
        if (j < lim) d += pp[j];
        v[u] = d;
        m = fmaxf(m, d);
    }
    #pragma unroll
    for (int o = 16; o; o >>= 1) m = fmaxf(m, __shfl_xor_sync(0xffffffffu, m, o));
    if ((tid & 31) == 0) red[tid >> 5] = m;
    __syncthreads();
    m = red[0];
    #pragma unroll
    for (int q = 1; q < 8; q++) m = fmaxf(m, red[q]);
    float s = 0.f;
    #pragma unroll
    for (int u = 0; u < 12; u++) { v[u] = __expf(v[u] - m); s += v[u]; }
    #pragma unroll
    for (int o = 16; o; o >>= 1) s += __shfl_xor_sync(0xffffffffu, s, o);
    if ((tid & 31) == 0) red2[tid >> 5] = s;
    __syncthreads();
    s = red2[0] + red2[1] + red2[2] + red2[3] + red2[4] + red2[5] + red2[6] + red2[7];
    float inv = 1.0f / s;
    #pragma unroll
    for (int u = 0; u < 12; u++) p[tid + (u << 8)] = v[u] * inv;
}

// ---------------- conv weight transpose: (O,I,4) -> (r*1024+ci, O) -------
__global__ void wtrans_kernel(const float* __restrict__ w) {
    long idx = (long)blockIdx.x * blockDim.x + threadIdx.x;
    if (idx >= 4096L * 1024) return;
    int k = (int)(idx >> 10);
    int o = (int)(idx & 1023);
    g_wt[idx] = w[(long)o * 4096 + ((k & 1023) << 2) + (k >> 10)];
}

// ---------------- simple vectorized copy + aux ---------------------------
__global__ void copy4_kernel(const float4* __restrict__ src, float4* __restrict__ dst, long n4) {
    long i = (long)blockIdx.x * blockDim.x + threadIdx.x;
    if (i < n4) dst[i] = src[i];
}
__global__ void aux_kernel(float* out) { *out = 0.f; }

// ---------------- launch ---------------------------------------------------
extern "C" void kernel_launch(void* const* d_in, const int* in_sizes, int n_in,
                              void* d_out_, int out_size) {
    const float* x      = (const float*)d_in[0];
    const float* mem    = (const float*)d_in[1];
    const float* cmem   = (const float*)d_in[2];
    const float* pos    = (const float*)d_in[3];
    const float* Wq     = (const float*)d_in[4];
    const float* Wkv    = (const float*)d_in[5];
    const float* Wout   = (const float*)d_in[6];
    const float* b_out  = (const float*)d_in[7];
    const float* conv_w = (const float*)d_in[8];
    const float* conv_b = (const float*)d_in[9];
    float* out = (float*)d_out_;

    float *p_kvin, *p_q, *p_kvout, *p_dots, *p_pos, *p_ctx, *p_wt;
    cudaGetSymbolAddress((void**)&p_kvin,  g_kv_in);
    cudaGetSymbolAddress((void**)&p_q,     g_q);
    cudaGetSymbolAddress((void**)&p_kvout, g_kv_out);
    cudaGetSymbolAddress((void**)&p_dots,  g_dots);
    cudaGetSymbolAddress((void**)&p_pos,   g_pos);
    cudaGetSymbolAddress((void**)&p_ctx,   g_ctx);
    cudaGetSymbolAddress((void**)&p_wt,    g_wt);

    // kv concat and projections (TF32 tensor cores)
    concat_kv_kernel<<<6144, 256>>>(x, mem, cmem);
    // q = x @ Wq           (M=2048, N=1024, K=1024)
    mma_gemm<128,128,64,32,false><<<dim3(8, 16, 1), 256>>>(
        x, Wq, nullptr, p_q, 1024, 1024, 1024, 1024, 1.0f, 1, 0,0, 0,0, 0,0);
    // kv = kv_in @ Wkv     (M=6144, N=2048, K=1024)
    mma_gemm<128,128,64,32,false><<<dim3(16, 48, 1), 256>>>(
        p_kvin, Wkv, nullptr, p_kvout, 1024, 1024, 2048, 2048, 1.0f, 1, 0,0, 0,0, 0,0);

    // dots[b,h] = SCALE * Q[b,h] @ K[b,h]^T   (M=1024, N=3072, K=64), z=b*16+h
    mma_gemm<128,128,64,32,true><<<dim3(24, 8, 32), 256>>>(
        p_q, p_kvout, nullptr, p_dots, 64, 1024, 2048, 3072, SCALE_F, 16,
        1048576L, 64L,            // A: b*1024*1024 + h*64
        6291456L, 64L,            // B: b*3072*2048 + h*64
        50331648L, 3145728L);     // C: (b*16+h)*1024*3072

    // P[b,h] = SCALE * Q[b,h] @ pos[h]^T      (M=1024, N=3072, K=64)
    mma_gemm<128,128,64,32,true><<<dim3(24, 8, 32), 256>>>(
        p_q, pos, nullptr, p_pos, 64, 1024, 64, 3072, SCALE_F, 16,
        1048576L, 64L,
        0L, 196608L,              // B: h*3072*64
        50331648L, 3145728L);

    // softmax with fused shifted positional add
    softmax_kernel<<<32768, 256>>>();

    // ctx[b,h] = attn[b,h] @ V[b,h]           (M=1024, N=64, K=3072)
    mma_gemm<128,64,32,32,false><<<dim3(1, 8, 32), 256>>>(
        p_dots, p_kvout + 1024, nullptr, p_ctx, 3072, 3072, 2048, 1024, 1.0f, 16,
        50331648L, 3145728L,      // A: (b*16+h)*1024*3072
        6291456L, 64L,            // B: b*3072*2048 + h*64 (+DD in base)
        1048576L, 64L);           // C: b*1024*1024 + h*64

    // logits = ctx @ Wout + b_out             (M=2048, N=1024, K=1024)
    mma_gemm<128,128,64,32,false><<<dim3(8, 16, 1), 256>>>(
        p_ctx, Wout, b_out, out, 1024, 1024, 1024, 1024, 1.0f, 1, 0,0, 0,0, 0,0);

    // new_mem = x
    copy4_kernel<<<2048, 256>>>((const float4*)x, (float4*)(out + 2097152), 524288);

    // new_cmem part 1: cmem[:, 256:] (768 rows per batch)
    copy4_kernel<<<768, 256>>>((const float4*)(cmem + 262144),  (float4*)(out + 4194304), 196608);
    copy4_kernel<<<768, 256>>>((const float4*)(cmem + 1310720), (float4*)(out + 5242880), 196608);

    // new_cmem part 2: strided conv as GEMM (M=256, K=4096, N=1024) per batch
    wtrans_kernel<<<16384, 256>>>(conv_w);
    mma_gemm<128,128,64,32,false><<<dim3(8, 2, 2), 256>>>(
        mem, p_wt, conv_b, out + 4980736, 4096, 4096, 1024, 1024, 1.0f, 1,
        1048576L, 0L, 0L, 0L, 1048576L, 0L);

    // aux_loss = 0
    aux_kernel<<<1, 1>>>(out + 6291456);
}

// round 5
// speedup vs baseline: 8.2715x; 1.1537x over previous
#include <cuda_runtime.h>

// Problem constants
#define BQ   2
#define TT   1024
#define DD   1024
#define HH   16
#define DHD  64
#define KVL  3072
#define MEML 1024
#define CMEML 1024
#define SCALE_F 0.125f

// ---------------- scratch (device globals; no allocation) ----------------
__device__ float g_kv_in [(long)BQ * KVL * DD];        //  6,291,456
__device__ float g_q     [(long)BQ * TT  * DD];        //  2,097,152
__device__ float g_kv_out[(long)BQ * KVL * 2 * DD];    // 12,582,912
__device__ float g_ctx   [(long)BQ * TT  * DD];        //  2,097,152
__device__ float g_wt    [4096L * 1024];               //  4,194,304

// ---------------- kv concat: [cmem, mem, x] -> g_kv_in -------------------
__global__ void concat_kv_kernel(const float* __restrict__ x,
                                 const float* __restrict__ mem,
                                 const float* __restrict__ cmem) {
    long i4 = (long)blockIdx.x * blockDim.x + threadIdx.x;
    const long total4 = (long)BQ * KVL * DD / 4;
    if (i4 >= total4) return;
    long e = i4 * 4;
    int  b   = (int)(e / ((long)KVL * DD));
    long rem = e - (long)b * KVL * DD;
    int  t   = (int)(rem / DD);
    int  c   = (int)(rem - (long)t * DD);
    const float* src;
    if (t < CMEML)              src = cmem + (long)b * CMEML * DD + (long)t * DD + c;
    else if (t < CMEML + MEML)  src = mem  + (long)b * MEML  * DD + (long)(t - CMEML) * DD + c;
    else                        src = x    + (long)b * TT    * DD + (long)(t - CMEML - MEML) * DD + c;
    *(float4*)(g_kv_in + e) = *(const float4*)src;
}

// ---------------- TF32 helpers ------------------------------------------
__device__ __forceinline__ unsigned f2tf(float f) {
    unsigned u;
    asm("cvt.rna.tf32.f32 %0, %1;" : "=r"(u) : "f"(f));
    return u;
}

__device__ __forceinline__ void mma_tf32(float c[4], const unsigned a[4], const unsigned b[2]) {
    asm volatile(
        "mma.sync.aligned.m16n8k8.row.col.f32.tf32.tf32.f32 "
        "{%0,%1,%2,%3},{%4,%5,%6,%7},{%8,%9},{%0,%1,%2,%3};"
        : "+f"(c[0]), "+f"(c[1]), "+f"(c[2]), "+f"(c[3])
        : "r"(a[0]), "r"(a[1]), "r"(a[2]), "r"(a[3]), "r"(b[0]), "r"(b[1]));
}

// ---------------- generic TF32 MMA GEMM (projections / conv) -------------
template<int BM, int BN, int WM, int WN, bool TRANSB>
__global__ __launch_bounds__(256) void mma_gemm(
    const float* __restrict__ A, const float* __restrict__ B,
    const float* __restrict__ bias, float* __restrict__ C,
    int K, int lda, int ldb, int ldc, float alpha, int ZH,
    long sAb, long sAh, long sBb, long sBh, long sCb, long sCh)
{
    constexpr int BK = 16;
    int z = blockIdx.z;
    int zb = z / ZH, zh = z - zb * ZH;
    A += (long)zb * sAb + (long)zh * sAh;
    B += (long)zb * sBb + (long)zh * sBh;
    C += (long)zb * sCb + (long)zh * sCh;
    int m0 = blockIdx.y * BM, n0 = blockIdx.x * BN;

    __shared__ unsigned As[2][BM][20];
    __shared__ unsigned Bs[2][TRANSB ? BN : BK][TRANSB ? 20 : BN + 8];

    int tid  = threadIdx.x;
    int warp = tid >> 5, lane = tid & 31;
    int gid  = lane >> 2, tg = lane & 3;
    constexpr int WNN = BN / WN;
    int wm = warp / WNN, wn = warp % WNN;
    constexpr int MI = WM / 16, NI = WN / 8;

    float acc[MI][NI][4];
    #pragma unroll
    for (int mi = 0; mi < MI; mi++)
        #pragma unroll
        for (int ni = 0; ni < NI; ni++)
            #pragma unroll
            for (int u = 0; u < 4; u++) acc[mi][ni][u] = 0.f;

    auto loadTiles = [&](int k0, int buf) {
        #pragma unroll
        for (int i = 0; i < BM / 64; i++) {
            int f = tid + i * 256;
            int r = f >> 2, c = (f & 3) << 2;
            float4 v = *(const float4*)(A + (long)(m0 + r) * lda + k0 + c);
            As[buf][r][c]     = f2tf(v.x);
            As[buf][r][c + 1] = f2tf(v.y);
            As[buf][r][c + 2] = f2tf(v.z);
            As[buf][r][c + 3] = f2tf(v.w);
        }
        if (TRANSB) {
            #pragma unroll
            for (int i = 0; i < BN / 64; i++) {
                int f = tid + i * 256;
                int r = f >> 2, c = (f & 3) << 2;
                float4 v = *(const float4*)(B + (long)(n0 + r) * ldb + k0 + c);
                Bs[buf][r][c]     = f2tf(v.x);
                Bs[buf][r][c + 1] = f2tf(v.y);
                Bs[buf][r][c + 2] = f2tf(v.z);
                Bs[buf][r][c + 3] = f2tf(v.w);
            }
        } else {
            constexpr int B4 = BN / 4;
            #pragma unroll
            for (int i = 0; i < BN / 64; i++) {
                int f = tid + i * 256;
                int r = f / B4, c = (f % B4) * 4;
                float4 v = *(const float4*)(B + (long)(k0 + r) * ldb + n0 + c);
                Bs[buf][r][c]     = f2tf(v.x);
                Bs[buf][r][c + 1] = f2tf(v.y);
                Bs[buf][r][c + 2] = f2tf(v.z);
                Bs[buf][r][c + 3] = f2tf(v.w);
            }
        }
    };

    loadTiles(0, 0);
    __syncthreads();
    int nk = K / BK;
    for (int kt = 0; kt < nk; kt++) {
        int buf = kt & 1;
        if (kt + 1 < nk) loadTiles((kt + 1) * BK, buf ^ 1);
        #pragma unroll
        for (int ks = 0; ks < 16; ks += 8) {
            unsigned af[MI][4], bf[NI][2];
            #pragma unroll
            for (int mi = 0; mi < MI; mi++) {
                int r = wm * WM + mi * 16;
                af[mi][0] = As[buf][r + gid][ks + tg];
                af[mi][1] = As[buf][r + gid + 8][ks + tg];
                af[mi][2] = As[buf][r + gid][ks + tg + 4];
                af[mi][3] = As[buf][r + gid + 8][ks + tg + 4];
            }
            #pragma unroll
            for (int ni = 0; ni < NI; ni++) {
                int cb = wn * WN + ni * 8;
                if (TRANSB) {
                    bf[ni][0] = Bs[buf][cb + gid][ks + tg];
                    bf[ni][1] = Bs[buf][cb + gid][ks + tg + 4];
                } else {
                    bf[ni][0] = Bs[buf][ks + tg][cb + gid];
                    bf[ni][1] = Bs[buf][ks + tg + 4][cb + gid];
                }
            }
            #pragma unroll
            for (int mi = 0; mi < MI; mi++)
                #pragma unroll
                for (int ni = 0; ni < NI; ni++)
                    mma_tf32(acc[mi][ni], af[mi], bf[ni]);
        }
        __syncthreads();
    }

    #pragma unroll
    for (int mi = 0; mi < MI; mi++) {
        #pragma unroll
        for (int ni = 0; ni < NI; ni++) {
            int r0 = m0 + wm * WM + mi * 16 + gid;
            int c  = n0 + wn * WN + ni * 8 + 2 * tg;
            float b0 = 0.f, b1 = 0.f;
            if (bias) { b0 = bias[c]; b1 = bias[c + 1]; }
            float2 v0 = make_float2(alpha * acc[mi][ni][0] + b0, alpha * acc[mi][ni][1] + b1);
            float2 v1 = make_float2(alpha * acc[mi][ni][2] + b0, alpha * acc[mi][ni][3] + b1);
            *(float2*)(C + (long)r0 * ldc + c)       = v0;
            *(float2*)(C + (long)(r0 + 8) * ldc + c) = v1;
        }
    }
}

// ---------------- fused flash attention (QK + shifted pos + softmax + AV) --
// Grid: (1, 8 i-tiles of 128, 32 bh). 256 threads = 8 warps; warp w owns rows
// 16w..16w+15 of the i-tile (full 64-col width) so softmax is quad-local.
// Dynamic smem layout (bytes):
//   Qs  [128][68] u32 @ 0        (34816)
//   Ks  [ 64][68] u32 @ 34816    (17408)
//   Vs  [ 64][72] u32 @ 52224    (18432)
//   Ps  [192][68] u32 @ 70656    (52224)   pos band rows
//   Pg  [128][84] f32 @ 122880   (43008)   per-warp band product / probs
#define FL_SMEM 165888

__global__ __launch_bounds__(256, 1) void flash_kernel(const float* __restrict__ pos) {
    extern __shared__ unsigned char sm[];
    unsigned (*Qs)[68] = (unsigned(*)[68])(sm);
    unsigned (*Ks)[68] = (unsigned(*)[68])(sm + 34816);
    unsigned (*Vs)[72] = (unsigned(*)[72])(sm + 52224);
    unsigned (*Ps)[68] = (unsigned(*)[68])(sm + 70656);
    float    (*Pg)[84] = (float   (*)[84])(sm + 122880);

    int bh = blockIdx.z; int b = bh >> 4, h = bh & 15;
    int i0 = blockIdx.y << 7;
    int tid = threadIdx.x, warp = tid >> 5, lane = tid & 31;
    int gid = lane >> 2, tg = lane & 3;

    // ---- load Q tile (scaled by SCALE so both QK and pos dots get it) ----
    {
        int r = tid >> 1, c0 = (tid & 1) << 5;
        const float* qp = g_q + ((long)(b * TT + i0 + r)) * DD + h * DHD + c0;
        #pragma unroll
        for (int u = 0; u < 8; u++) {
            float4 v = *(const float4*)(qp + 4 * u);
            uint4 t;
            t.x = f2tf(v.x * SCALE_F); t.y = f2tf(v.y * SCALE_F);
            t.z = f2tf(v.z * SCALE_F); t.w = f2tf(v.w * SCALE_F);
            *(uint4*)&Qs[r][c0 + 4 * u] = t;
        }
    }
    __syncthreads();

    float oacc[8][4];
    #pragma unroll
    for (int nb = 0; nb < 8; nb++)
        #pragma unroll
        for (int u = 0; u < 4; u++) oacc[nb][u] = 0.f;
    float m0r = -1e30f, m1r = -1e30f, l0r = 0.f, l1r = 0.f;

    int wb = 112 - (warp << 4);          // warp's band window start in Ps
    int arow = (warp << 4) + gid;        // warp's A rows (and +8)
    int pgr0 = (warp << 4) + gid;        // Pg rows
    int pgr1 = pgr0 + 8;

    for (int j0 = 0; j0 < KVL; j0 += 64) {
        // ---- cooperative loads: K, V, pos band ----
        {
            int r = tid >> 2, c0 = (tid & 3) << 4;
            const float* kp = g_kv_out + ((long)(b * KVL + j0 + r)) * (2 * DD) + h * DHD + c0;
            #pragma unroll
            for (int u = 0; u < 4; u++) {
                float4 v = *(const float4*)(kp + 4 * u);
                uint4 t; t.x = f2tf(v.x); t.y = f2tf(v.y); t.z = f2tf(v.z); t.w = f2tf(v.w);
                *(uint4*)&Ks[r][c0 + 4 * u] = t;
            }
            const float* vp = kp + DD;
            #pragma unroll
            for (int u = 0; u < 4; u++) {
                float4 v = *(const float4*)(vp + 4 * u);
                uint4 t; t.x = f2tf(v.x); t.y = f2tf(v.y); t.z = f2tf(v.z); t.w = f2tf(v.w);
                *(uint4*)&Vs[r][c0 + 4 * u] = t;
            }
            int ubase = j0 + 896 - i0;   // u for band row 0 (always >= 0)
            #pragma unroll
            for (int it = 0; it < 3; it++) {
                int rr = r + it * 64;
                int u = ubase + rr;
                if (u < KVL) {
                    const float* pp = pos + ((long)h * KVL + u) * DHD + c0;
                    #pragma unroll
                    for (int q = 0; q < 4; q++) {
                        float4 v = *(const float4*)(pp + 4 * q);
                        uint4 t; t.x = f2tf(v.x); t.y = f2tf(v.y); t.z = f2tf(v.z); t.w = f2tf(v.w);
                        *(uint4*)&Ps[rr][c0 + 4 * q] = t;
                    }
                } else {
                    uint4 z = make_uint4(0, 0, 0, 0);
                    #pragma unroll
                    for (int q = 0; q < 4; q++) *(uint4*)&Ps[rr][c0 + 4 * q] = z;
                }
            }
        }
        __syncthreads();

        // ---- S = QK^T and band product Pb = Q @ posband^T ----
        float sacc[8][4], pacc[10][4];
        #pragma unroll
        for (int nb = 0; nb < 8; nb++)
            #pragma unroll
            for (int u = 0; u < 4; u++) sacc[nb][u] = 0.f;
        #pragma unroll
        for (int nb = 0; nb < 10; nb++)
            #pragma unroll
            for (int u = 0; u < 4; u++) pacc[nb][u] = 0.f;

        #pragma unroll
        for (int kb = 0; kb < 8; kb++) {
            unsigned af[4];
            af[0] = Qs[arow][kb * 8 + tg];
            af[1] = Qs[arow + 8][kb * 8 + tg];
            af[2] = Qs[arow][kb * 8 + tg + 4];
            af[3] = Qs[arow + 8][kb * 8 + tg + 4];
            #pragma unroll
            for (int nb = 0; nb < 8; nb++) {
                unsigned bf[2] = { Ks[nb * 8 + gid][kb * 8 + tg],
                                   Ks[nb * 8 + gid][kb * 8 + tg + 4] };
                mma_tf32(sacc[nb], af, bf);
            }
            #pragma unroll
            for (int nb = 0; nb < 10; nb++) {
                unsigned bf[2] = { Ps[wb + nb * 8 + gid][kb * 8 + tg],
                                   Ps[wb + nb * 8 + gid][kb * 8 + tg + 4] };
                mma_tf32(pacc[nb], af, bf);
            }
        }

        // ---- dump band product, gather shifted into S ----
        #pragma unroll
        for (int nb = 0; nb < 10; nb++) {
            Pg[pgr0][nb * 8 + 2 * tg]     = pacc[nb][0];
            Pg[pgr0][nb * 8 + 2 * tg + 1] = pacc[nb][1];
            Pg[pgr1][nb * 8 + 2 * tg]     = pacc[nb][2];
            Pg[pgr1][nb * 8 + 2 * tg + 1] = pacc[nb][3];
        }
        __syncwarp();
        {
            int s0 = 15 - gid, s1 = 7 - gid;
            #pragma unroll
            for (int nb = 0; nb < 8; nb++) {
                int jl = nb * 8 + 2 * tg;
                sacc[nb][0] += Pg[pgr0][jl + s0];
                sacc[nb][1] += Pg[pgr0][jl + 1 + s0];
                sacc[nb][2] += Pg[pgr1][jl + s1];
                sacc[nb][3] += Pg[pgr1][jl + 1 + s1];
            }
        }

        // ---- online softmax (rows quad-local) ----
        float mx0 = -1e30f, mx1 = -1e30f;
        #pragma unroll
        for (int nb = 0; nb < 8; nb++) {
            mx0 = fmaxf(mx0, fmaxf(sacc[nb][0], sacc[nb][1]));
            mx1 = fmaxf(mx1, fmaxf(sacc[nb][2], sacc[nb][3]));
        }
        #pragma unroll
        for (int o = 1; o <= 2; o <<= 1) {
            mx0 = fmaxf(mx0, __shfl_xor_sync(0xffffffffu, mx0, o));
            mx1 = fmaxf(mx1, __shfl_xor_sync(0xffffffffu, mx1, o));
        }
        float mn0 = fmaxf(m0r, mx0), mn1 = fmaxf(m1r, mx1);
        float f0 = __expf(m0r - mn0), f1 = __expf(m1r - mn1);
        m0r = mn0; m1r = mn1;
        float ps0 = 0.f, ps1 = 0.f;
        #pragma unroll
        for (int nb = 0; nb < 8; nb++) {
            sacc[nb][0] = __expf(sacc[nb][0] - mn0);
            sacc[nb][1] = __expf(sacc[nb][1] - mn0);
            sacc[nb][2] = __expf(sacc[nb][2] - mn1);
            sacc[nb][3] = __expf(sacc[nb][3] - mn1);
            ps0 += sacc[nb][0] + sacc[nb][1];
            ps1 += sacc[nb][2] + sacc[nb][3];
            oacc[nb][0] *= f0; oacc[nb][1] *= f0;
            oacc[nb][2] *= f1; oacc[nb][3] *= f1;
        }
        #pragma unroll
        for (int o = 1; o <= 2; o <<= 1) {
            ps0 += __shfl_xor_sync(0xffffffffu, ps0, o);
            ps1 += __shfl_xor_sync(0xffffffffu, ps1, o);
        }
        l0r = l0r * f0 + ps0;
        l1r = l1r * f1 + ps1;

        // ---- probs -> smem (tf32) -> A fragments for AV ----
        __syncwarp();
        #pragma unroll
        for (int nb = 0; nb < 8; nb++) {
            Pg[pgr0][nb * 8 + 2 * tg]     = __uint_as_float(f2tf(sacc[nb][0]));
            Pg[pgr0][nb * 8 + 2 * tg + 1] = __uint_as_float(f2tf(sacc[nb][1]));
            Pg[pgr1][nb * 8 + 2 * tg]     = __uint_as_float(f2tf(sacc[nb][2]));
            Pg[pgr1][nb * 8 + 2 * tg + 1] = __uint_as_float(f2tf(sacc[nb][3]));
        }
        __syncwarp();

        #pragma unroll
        for (int kb = 0; kb < 8; kb++) {
            unsigned af[4];
            af[0] = __float_as_uint(Pg[pgr0][kb * 8 + tg]);
            af[1] = __float_as_uint(Pg[pgr1][kb * 8 + tg]);
            af[2] = __float_as_uint(Pg[pgr0][kb * 8 + tg + 4]);
            af[3] = __float_as_uint(Pg[pgr1][kb * 8 + tg + 4]);
            #pragma unroll
            for (int nb = 0; nb < 8; nb++) {
                unsigned bf[2] = { Vs[kb * 8 + tg][nb * 8 + gid],
                                   Vs[kb * 8 + tg + 4][nb * 8 + gid] };
                mma_tf32(oacc[nb], af, bf);
            }
        }
        __syncthreads();
    }

    // ---- write ctx = O / l ----
    float inv0 = 1.0f / l0r, inv1 = 1.0f / l1r;
    #pragma unroll
    for (int nb = 0; nb < 8; nb++) {
        int c = h * DHD + nb * 8 + 2 * tg;
        long r0 = (long)(b * TT + i0 + (warp << 4) + gid) * DD + c;
        *(float2*)(g_ctx + r0)            = make_float2(oacc[nb][0] * inv0, oacc[nb][1] * inv0);
        *(float2*)(g_ctx + r0 + 8 * DD)   = make_float2(oacc[nb][2] * inv1, oacc[nb][3] * inv1);
    }
}

// ---------------- conv weight transpose: (O,I,4) -> (r*1024+ci, O) -------
__global__ void wtrans_kernel(const float* __restrict__ w) {
    long idx = (long)blockIdx.x * blockDim.x + threadIdx.x;
    if (idx >= 4096L * 1024) return;
    int k = (int)(idx >> 10);
    int o = (int)(idx & 1023);
    g_wt[idx] = w[(long)o * 4096 + ((k & 1023) << 2) + (k >> 10)];
}

// ---------------- simple vectorized copy + aux ---------------------------
__global__ void copy4_kernel(const float4* __restrict__ src, float4* __restrict__ dst, long n4) {
    long i = (long)blockIdx.x * blockDim.x + threadIdx.x;
    if (i < n4) dst[i] = src[i];
}
__global__ void aux_kernel(float* out) { *out = 0.f; }

// ---------------- launch ---------------------------------------------------
extern "C" void kernel_launch(void* const* d_in, const int* in_sizes, int n_in,
                              void* d_out_, int out_size) {
    const float* x      = (const float*)d_in[0];
    const float* mem    = (const float*)d_in[1];
    const float* cmem   = (const float*)d_in[2];
    const float* pos    = (const float*)d_in[3];
    const float* Wq     = (const float*)d_in[4];
    const float* Wkv    = (const float*)d_in[5];
    const float* Wout   = (const float*)d_in[6];
    const float* b_out  = (const float*)d_in[7];
    const float* conv_w = (const float*)d_in[8];
    const float* conv_b = (const float*)d_in[9];
    float* out = (float*)d_out_;

    float *p_kvin, *p_q, *p_kvout, *p_ctx, *p_wt;
    cudaGetSymbolAddress((void**)&p_kvin,  g_kv_in);
    cudaGetSymbolAddress((void**)&p_q,     g_q);
    cudaGetSymbolAddress((void**)&p_kvout, g_kv_out);
    cudaGetSymbolAddress((void**)&p_ctx,   g_ctx);
    cudaGetSymbolAddress((void**)&p_wt,    g_wt);

    cudaFuncSetAttribute(flash_kernel, cudaFuncAttributeMaxDynamicSharedMemorySize, FL_SMEM);

    // kv concat and projections (TF32 tensor cores)
    concat_kv_kernel<<<6144, 256>>>(x, mem, cmem);
    // q = x @ Wq           (M=2048, N=1024, K=1024)
    mma_gemm<128,128,64,32,false><<<dim3(8, 16, 1), 256>>>(
        x, Wq, nullptr, p_q, 1024, 1024, 1024, 1024, 1.0f, 1, 0,0, 0,0, 0,0);
    // kv = kv_in @ Wkv     (M=6144, N=2048, K=1024)
    mma_gemm<128,128,64,32,false><<<dim3(16, 48, 1), 256>>>(
        p_kvin, Wkv, nullptr, p_kvout, 1024, 1024, 2048, 2048, 1.0f, 1, 0,0, 0,0, 0,0);

    // fused attention: dots + shifted pos + softmax + AV -> g_ctx
    flash_kernel<<<dim3(1, 8, 32), 256, FL_SMEM>>>(pos);

    // logits = ctx @ Wout + b_out             (M=2048, N=1024, K=1024)
    mma_gemm<128,128,64,32,false><<<dim3(8, 16, 1), 256>>>(
        p_ctx, Wout, b_out, out, 1024, 1024, 1024, 1024, 1.0f, 1, 0,0, 0,0, 0,0);

    // new_mem = x
    copy4_kernel<<<2048, 256>>>((const float4*)x, (float4*)(out + 2097152), 524288);

    // new_cmem part 1: cmem[:, 256:] (768 rows per batch)
    copy4_kernel<<<768, 256>>>((const float4*)(cmem + 262144),  (float4*)(out + 4194304), 196608);
    copy4_kernel<<<768, 256>>>((const float4*)(cmem + 1310720), (float4*)(out + 5242880), 196608);

    // new_cmem part 2: strided conv as GEMM (M=256, K=4096, N=1024) per batch
    wtrans_kernel<<<16384, 256>>>(conv_w);
    mma_gemm<128,128,64,32,false><<<dim3(8, 2, 2), 256>>>(
        mem, p_wt, conv_b, out + 4980736, 4096, 4096, 1024, 1024, 1.0f, 1,
        1048576L, 0L, 0L, 0L, 1048576L, 0L);

    // aux_loss = 0
    aux_kernel<<<1, 1>>>(out + 6291456);
}

// round 6
// speedup vs baseline: 10.0125x; 1.2105x over previous
#include <cuda_runtime.h>

// Problem constants
#define BQ   2
#define TT   1024
#define DD   1024
#define HH   16
#define DHD  64
#define KVL  3072
#define MEML 1024
#define CMEML 1024
#define SCALE_F 0.125f

// ---------------- scratch (device globals; no allocation) ----------------
__device__ float g_kv_in [(long)BQ * KVL * DD];        // tf32 bits
__device__ float g_q     [(long)BQ * TT  * DD];        // tf32 bits, pre-scaled
__device__ float g_kv_out[(long)BQ * KVL * 2 * DD];    // tf32 bits
__device__ float g_ctx   [(long)BQ * TT  * DD];        // tf32 bits
__device__ float g_wt    [4096L * 1024];               // tf32 bits
__device__ float g_xtf   [(long)BQ * TT * DD];
__device__ float g_wqt   [1024L * 1024];
__device__ float g_wkvt  [1024L * 2048];
__device__ float g_woutt [1024L * 1024];
__device__ float g_memtf [(long)BQ * MEML * DD];
__device__ float g_ptf   [(long)HH * KVL * DHD];

// ---------------- TF32 + cp.async helpers --------------------------------
__device__ __forceinline__ unsigned f2tf(float f) {
    unsigned u;
    asm("cvt.rna.tf32.f32 %0, %1;" : "=r"(u) : "f"(f));
    return u;
}
__device__ __forceinline__ void mma_tf32(float c[4], const unsigned a[4], const unsigned b[2]) {
    asm volatile(
        "mma.sync.aligned.m16n8k8.row.col.f32.tf32.tf32.f32 "
        "{%0,%1,%2,%3},{%4,%5,%6,%7},{%8,%9},{%0,%1,%2,%3};"
        : "+f"(c[0]), "+f"(c[1]), "+f"(c[2]), "+f"(c[3])
        : "r"(a[0]), "r"(a[1]), "r"(a[2]), "r"(a[3]), "r"(b[0]), "r"(b[1]));
}
__device__ __forceinline__ void cp16(void* s, const void* g) {
    unsigned a = (unsigned)__cvta_generic_to_shared(s);
    asm volatile("cp.async.cg.shared.global [%0], [%1], 16;" :: "r"(a), "l"(g));
}
__device__ __forceinline__ void cp_commit() { asm volatile("cp.async.commit_group;"); }
template<int N> __device__ __forceinline__ void cp_wait() {
    asm volatile("cp.async.wait_group %0;" :: "n"(N));
}

// ---------------- convert fp32 -> tf32 bits ------------------------------
__global__ void cvt_kernel(const float4* __restrict__ src, float* __restrict__ dst, long n4) {
    long i = (long)blockIdx.x * blockDim.x + threadIdx.x;
    if (i >= n4) return;
    float4 v = src[i];
    uint4 t;
    t.x = f2tf(v.x); t.y = f2tf(v.y); t.z = f2tf(v.z); t.w = f2tf(v.w);
    *(uint4*)(dst + i * 4) = t;
}

// ---------------- kv concat: [cmem, mem, x] -> g_kv_in (tf32) -------------
__global__ void concat_kv_kernel(const float* __restrict__ x,
                                 const float* __restrict__ mem,
                                 const float* __restrict__ cmem) {
    long i4 = (long)blockIdx.x * blockDim.x + threadIdx.x;
    const long total4 = (long)BQ * KVL * DD / 4;
    if (i4 >= total4) return;
    long e = i4 * 4;
    int  b   = (int)(e / ((long)KVL * DD));
    long rem = e - (long)b * KVL * DD;
    int  t   = (int)(rem / DD);
    int  c   = (int)(rem - (long)t * DD);
    const float* src;
    if (t < CMEML)              src = cmem + (long)b * CMEML * DD + (long)t * DD + c;
    else if (t < CMEML + MEML)  src = mem  + (long)b * MEML  * DD + (long)(t - CMEML) * DD + c;
    else                        src = x    + (long)b * TT    * DD + (long)(t - CMEML - MEML) * DD + c;
    float4 v = *(const float4*)src;
    uint4 tv;
    tv.x = f2tf(v.x); tv.y = f2tf(v.y); tv.z = f2tf(v.z); tv.w = f2tf(v.w);
    *(uint4*)(g_kv_in + e) = tv;
}

// ---------------- async TF32 MMA GEMM (inputs pre-converted) --------------
// C = alpha * A(MxK) @ B(KxN) [+ bias]. TF32OUT: write f2tf(alpha*acc) bits.
template<int BM, int BN, int WM, int WN, bool TF32OUT>
__global__ __launch_bounds__(256) void mma_gemm_async(
    const float* __restrict__ A, const float* __restrict__ B,
    const float* __restrict__ bias, float* __restrict__ C,
    int K, int lda, int ldb, int ldc, float alpha, int ZH,
    long sAb, long sAh, long sBb, long sBh, long sCb, long sCh)
{
    int z = blockIdx.z;
    int zb = z / ZH, zh = z - zb * ZH;
    A += (long)zb * sAb + (long)zh * sAh;
    B += (long)zb * sBb + (long)zh * sBh;
    C += (long)zb * sCb + (long)zh * sCh;
    int m0 = blockIdx.y * BM, n0 = blockIdx.x * BN;

    __shared__ __align__(16) unsigned As[2][BM][20];
    __shared__ __align__(16) unsigned Bs[2][16][BN + 8];

    int tid  = threadIdx.x;
    int warp = tid >> 5, lane = tid & 31;
    int gid  = lane >> 2, tg = lane & 3;
    constexpr int WNN = BN / WN;
    int wm = warp / WNN, wn = warp % WNN;
    constexpr int MI = WM / 16, NI = WN / 8;

    float acc[MI][NI][4];
    #pragma unroll
    for (int mi = 0; mi < MI; mi++)
        #pragma unroll
        for (int ni = 0; ni < NI; ni++)
            #pragma unroll
            for (int u = 0; u < 4; u++) acc[mi][ni][u] = 0.f;

    auto issueTiles = [&](int k0, int buf) {
        #pragma unroll
        for (int i = 0; i < BM / 64; i++) {
            int f = tid + i * 256;
            int r = f >> 2, c = (f & 3) << 2;
            cp16(&As[buf][r][c], A + (long)(m0 + r) * lda + k0 + c);
        }
        constexpr int B4 = BN / 4;
        #pragma unroll
        for (int i = 0; i < BN / 64; i++) {
            int f = tid + i * 256;
            int r = f / B4, c = (f % B4) * 4;
            cp16(&Bs[buf][r][c], B + (long)(k0 + r) * ldb + n0 + c);
        }
        cp_commit();
    };

    issueTiles(0, 0);
    int nk = K / 16;
    for (int kt = 0; kt < nk; kt++) {
        int buf = kt & 1;
        if (kt + 1 < nk) {
            __syncthreads();
            issueTiles((kt + 1) * 16, buf ^ 1);
            cp_wait<1>();
        } else {
            cp_wait<0>();
        }
        __syncthreads();
        #pragma unroll
        for (int ks = 0; ks < 16; ks += 8) {
            unsigned af[MI][4], bf[NI][2];
            #pragma unroll
            for (int mi = 0; mi < MI; mi++) {
                int r = wm * WM + mi * 16;
                af[mi][0] = As[buf][r + gid][ks + tg];
                af[mi][1] = As[buf][r + gid + 8][ks + tg];
                af[mi][2] = As[buf][r + gid][ks + tg + 4];
                af[mi][3] = As[buf][r + gid + 8][ks + tg + 4];
            }
            #pragma unroll
            for (int ni = 0; ni < NI; ni++) {
                int cb = wn * WN + ni * 8;
                bf[ni][0] = Bs[buf][ks + tg][cb + gid];
                bf[ni][1] = Bs[buf][ks + tg + 4][cb + gid];
            }
            #pragma unroll
            for (int mi = 0; mi < MI; mi++)
                #pragma unroll
                for (int ni = 0; ni < NI; ni++)
                    mma_tf32(acc[mi][ni], af[mi], bf[ni]);
        }
    }

    #pragma unroll
    for (int mi = 0; mi < MI; mi++) {
        #pragma unroll
        for (int ni = 0; ni < NI; ni++) {
            int r0 = m0 + wm * WM + mi * 16 + gid;
            int c  = n0 + wn * WN + ni * 8 + 2 * tg;
            if (TF32OUT) {
                uint2 v0 = make_uint2(f2tf(alpha * acc[mi][ni][0]), f2tf(alpha * acc[mi][ni][1]));
                uint2 v1 = make_uint2(f2tf(alpha * acc[mi][ni][2]), f2tf(alpha * acc[mi][ni][3]));
                *(uint2*)(C + (long)r0 * ldc + c)       = v0;
                *(uint2*)(C + (long)(r0 + 8) * ldc + c) = v1;
            } else {
                float b0 = 0.f, b1 = 0.f;
                if (bias) { b0 = bias[c]; b1 = bias[c + 1]; }
                float2 v0 = make_float2(alpha * acc[mi][ni][0] + b0, alpha * acc[mi][ni][1] + b1);
                float2 v1 = make_float2(alpha * acc[mi][ni][2] + b0, alpha * acc[mi][ni][3] + b1);
                *(float2*)(C + (long)r0 * ldc + c)       = v0;
                *(float2*)(C + (long)(r0 + 8) * ldc + c) = v1;
            }
        }
    }
}

// ---------------- fused flash attention (cp.async double-buffered) --------
// smem: Ks[2][64][68] @0 (34816) | Vs[2][64][72] @34816 (36864)
//       Ps[2][192][68] @71680 (104448) | Pg[128][84] @176128 (43008) = 219136
#define FL_SMEM 219136

__global__ __launch_bounds__(256, 1) void flash_kernel(const float* __restrict__ pos_tf) {
    extern __shared__ __align__(16) unsigned char sm[];
    unsigned (*Ks)[64][68]  = (unsigned(*)[64][68]) (sm);
    unsigned (*Vs)[64][72]  = (unsigned(*)[64][72]) (sm + 34816);
    unsigned (*Ps)[192][68] = (unsigned(*)[192][68])(sm + 71680);
    float    (*Pg)[84]      = (float(*)[84])        (sm + 176128);

    int bh = blockIdx.z; int b = bh >> 4, h = bh & 15;
    int i0 = blockIdx.y << 7;
    int tid = threadIdx.x, warp = tid >> 5, lane = tid & 31;
    int gid = lane >> 2, tg = lane & 3;

    // Q fragments in registers (g_q already scaled & tf32)
    unsigned qf[8][4];
    {
        const float* q0 = g_q + (long)(b * TT + i0 + (warp << 4) + gid) * DD + h * DHD;
        const float* q1 = q0 + 8 * DD;
        #pragma unroll
        for (int kb = 0; kb < 8; kb++) {
            qf[kb][0] = __float_as_uint(q0[kb * 8 + tg]);
            qf[kb][1] = __float_as_uint(q1[kb * 8 + tg]);
            qf[kb][2] = __float_as_uint(q0[kb * 8 + tg + 4]);
            qf[kb][3] = __float_as_uint(q1[kb * 8 + tg + 4]);
        }
    }

    int r = tid >> 2, cw = (tid & 3) << 4;
    const float* kvbase = g_kv_out + ((long)(b * KVL) + r) * (2 * DD) + h * DHD + cw;
    int ubase0 = 896 - i0;

    auto issue = [&](int j0, int buf) {
        const float* kp = kvbase + (long)j0 * (2 * DD);
        #pragma unroll
        for (int u = 0; u < 4; u++) cp16(&Ks[buf][r][cw + 4 * u], kp + 4 * u);
        const float* vp = kp + DD;
        #pragma unroll
        for (int u = 0; u < 4; u++) cp16(&Vs[buf][r][cw + 4 * u], vp + 4 * u);
        int ub = j0 + ubase0;
        #pragma unroll
        for (int it = 0; it < 3; it++) {
            int rr = r + it * 64;
            int uu = ub + rr;
            if (uu < KVL) {
                const float* pp = pos_tf + ((long)h * KVL + uu) * DHD + cw;
                #pragma unroll
                for (int q = 0; q < 4; q++) cp16(&Ps[buf][rr][cw + 4 * q], pp + 4 * q);
            } else {
                uint4 z = make_uint4(0, 0, 0, 0);
                #pragma unroll
                for (int q = 0; q < 4; q++) *(uint4*)&Ps[buf][rr][cw + 4 * q] = z;
            }
        }
        cp_commit();
    };

    float oacc[8][4] = {};
    float m0r = -1e30f, m1r = -1e30f, l0r = 0.f, l1r = 0.f;
    int wb = 112 - (warp << 4);
    int pgr0 = (warp << 4) + gid, pgr1 = pgr0 + 8;

    issue(0, 0);
    for (int t = 0; t < 48; t++) {
        int buf = t & 1;
        if (t < 47) {
            __syncthreads();
            issue((t + 1) << 6, buf ^ 1);
            cp_wait<1>();
        } else {
            cp_wait<0>();
        }
        __syncthreads();

        // ---- S = QK^T and band product ----
        float sacc[8][4] = {}, pacc[10][4] = {};
        #pragma unroll
        for (int kb = 0; kb < 8; kb++) {
            #pragma unroll
            for (int nb = 0; nb < 8; nb++) {
                unsigned bf[2] = { Ks[buf][nb * 8 + gid][kb * 8 + tg],
                                   Ks[buf][nb * 8 + gid][kb * 8 + tg + 4] };
                mma_tf32(sacc[nb], qf[kb], bf);
            }
            #pragma unroll
            for (int nb = 0; nb < 10; nb++) {
                unsigned bf[2] = { Ps[buf][wb + nb * 8 + gid][kb * 8 + tg],
                                   Ps[buf][wb + nb * 8 + gid][kb * 8 + tg + 4] };
                mma_tf32(pacc[nb], qf[kb], bf);
            }
        }

        // ---- dump band product, gather shifted into S ----
        #pragma unroll
        for (int nb = 0; nb < 10; nb++) {
            Pg[pgr0][nb * 8 + 2 * tg]     = pacc[nb][0];
            Pg[pgr0][nb * 8 + 2 * tg + 1] = pacc[nb][1];
            Pg[pgr1][nb * 8 + 2 * tg]     = pacc[nb][2];
            Pg[pgr1][nb * 8 + 2 * tg + 1] = pacc[nb][3];
        }
        __syncwarp();
        {
            int s0 = 15 - gid, s1 = 7 - gid;
            #pragma unroll
            for (int nb = 0; nb < 8; nb++) {
                int jl = nb * 8 + 2 * tg;
                sacc[nb][0] += Pg[pgr0][jl + s0];
                sacc[nb][1] += Pg[pgr0][jl + 1 + s0];
                sacc[nb][2] += Pg[pgr1][jl + s1];
                sacc[nb][3] += Pg[pgr1][jl + 1 + s1];
            }
        }

        // ---- online softmax (rows quad-local) ----
        float mx0 = -1e30f, mx1 = -1e30f;
        #pragma unroll
        for (int nb = 0; nb < 8; nb++) {
            mx0 = fmaxf(mx0, fmaxf(sacc[nb][0], sacc[nb][1]));
            mx1 = fmaxf(mx1, fmaxf(sacc[nb][2], sacc[nb][3]));
        }
        #pragma unroll
        for (int o = 1; o <= 2; o <<= 1) {
            mx0 = fmaxf(mx0, __shfl_xor_sync(0xffffffffu, mx0, o));
            mx1 = fmaxf(mx1, __shfl_xor_sync(0xffffffffu, mx1, o));
        }
        float mn0 = fmaxf(m0r, mx0), mn1 = fmaxf(m1r, mx1);
        float f0 = __expf(m0r - mn0), f1 = __expf(m1r - mn1);
        m0r = mn0; m1r = mn1;
        float ps0 = 0.f, ps1 = 0.f;
        #pragma unroll
        for (int nb = 0; nb < 8; nb++) {
            sacc[nb][0] = __expf(sacc[nb][0] - mn0);
            sacc[nb][1] = __expf(sacc[nb][1] - mn0);
            sacc[nb][2] = __expf(sacc[nb][2] - mn1);
            sacc[nb][3] = __expf(sacc[nb][3] - mn1);
            ps0 += sacc[nb][0] + sacc[nb][1];
            ps1 += sacc[nb][2] + sacc[nb][3];
            oacc[nb][0] *= f0; oacc[nb][1] *= f0;
            oacc[nb][2] *= f1; oacc[nb][3] *= f1;
        }
        #pragma unroll
        for (int o = 1; o <= 2; o <<= 1) {
            ps0 += __shfl_xor_sync(0xffffffffu, ps0, o);
            ps1 += __shfl_xor_sync(0xffffffffu, ps1, o);
        }
        l0r = l0r * f0 + ps0;
        l1r = l1r * f1 + ps1;

        // ---- probs -> smem (tf32) -> A fragments for AV ----
        __syncwarp();
        #pragma unroll
        for (int nb = 0; nb < 8; nb++) {
            Pg[pgr0][nb * 8 + 2 * tg]     = __uint_as_float(f2tf(sacc[nb][0]));
            Pg[pgr0][nb * 8 + 2 * tg + 1] = __uint_as_float(f2tf(sacc[nb][1]));
            Pg[pgr1][nb * 8 + 2 * tg]     = __uint_as_float(f2tf(sacc[nb][2]));
            Pg[pgr1][nb * 8 + 2 * tg + 1] = __uint_as_float(f2tf(sacc[nb][3]));
        }
        __syncwarp();

        #pragma unroll
        for (int kb = 0; kb < 8; kb++) {
            unsigned af[4];
            af[0] = __float_as_uint(Pg[pgr0][kb * 8 + tg]);
            af[1] = __float_as_uint(Pg[pgr1][kb * 8 + tg]);
            af[2] = __float_as_uint(Pg[pgr0][kb * 8 + tg + 4]);
            af[3] = __float_as_uint(Pg[pgr1][kb * 8 + tg + 4]);
            #pragma unroll
            for (int nb = 0; nb < 8; nb++) {
                unsigned bf[2] = { Vs[buf][kb * 8 + tg][nb * 8 + gid],
                                   Vs[buf][kb * 8 + tg + 4][nb * 8 + gid] };
                mma_tf32(oacc[nb], af, bf);
            }
        }
    }

    // ---- write ctx = O / l as tf32 bits (consumed by out-proj GEMM) ----
    float inv0 = 1.0f / l0r, inv1 = 1.0f / l1r;
    #pragma unroll
    for (int nb = 0; nb < 8; nb++) {
        int c = h * DHD + nb * 8 + 2 * tg;
        long r0 = (long)(b * TT + i0 + (warp << 4) + gid) * DD + c;
        uint2 v0 = make_uint2(f2tf(oacc[nb][0] * inv0), f2tf(oacc[nb][1] * inv0));
        uint2 v1 = make_uint2(f2tf(oacc[nb][2] * inv1), f2tf(oacc[nb][3] * inv1));
        *(uint2*)(g_ctx + r0)          = v0;
        *(uint2*)(g_ctx + r0 + 8 * DD) = v1;
    }
}

// ---------------- conv weight transpose (tf32 out) ------------------------
__global__ void wtrans_kernel(const float* __restrict__ w) {
    long idx = (long)blockIdx.x * blockDim.x + threadIdx.x;
    if (idx >= 4096L * 1024) return;
    int k = (int)(idx >> 10);
    int o = (int)(idx & 1023);
    g_wt[idx] = __uint_as_float(f2tf(w[(long)o * 4096 + ((k & 1023) << 2) + (k >> 10)]));
}

// ---------------- simple vectorized copy + aux ---------------------------
__global__ void copy4_kernel(const float4* __restrict__ src, float4* __restrict__ dst, long n4) {
    long i = (long)blockIdx.x * blockDim.x + threadIdx.x;
    if (i < n4) dst[i] = src[i];
}
__global__ void aux_kernel(float* out) { *out = 0.f; }

// ---------------- launch ---------------------------------------------------
extern "C" void kernel_launch(void* const* d_in, const int* in_sizes, int n_in,
                              void* d_out_, int out_size) {
    const float* x      = (const float*)d_in[0];
    const float* mem    = (const float*)d_in[1];
    const float* cmem   = (const float*)d_in[2];
    const float* pos    = (const float*)d_in[3];
    const float* Wq     = (const float*)d_in[4];
    const float* Wkv    = (const float*)d_in[5];
    const float* Wout   = (const float*)d_in[6];
    const float* b_out  = (const float*)d_in[7];
    const float* conv_w = (const float*)d_in[8];
    const float* conv_b = (const float*)d_in[9];
    float* out = (float*)d_out_;

    float *p_kvin, *p_q, *p_kvout, *p_ctx, *p_wt;
    float *p_xtf, *p_wqt, *p_wkvt, *p_woutt, *p_memtf, *p_ptf;
    cudaGetSymbolAddress((void**)&p_kvin,  g_kv_in);
    cudaGetSymbolAddress((void**)&p_q,     g_q);
    cudaGetSymbolAddress((void**)&p_kvout, g_kv_out);
    cudaGetSymbolAddress((void**)&p_ctx,   g_ctx);
    cudaGetSymbolAddress((void**)&p_wt,    g_wt);
    cudaGetSymbolAddress((void**)&p_xtf,   g_xtf);
    cudaGetSymbolAddress((void**)&p_wqt,   g_wqt);
    cudaGetSymbolAddress((void**)&p_wkvt,  g_wkvt);
    cudaGetSymbolAddress((void**)&p_woutt, g_woutt);
    cudaGetSymbolAddress((void**)&p_memtf, g_memtf);
    cudaGetSymbolAddress((void**)&p_ptf,   g_ptf);

    cudaFuncSetAttribute(flash_kernel, cudaFuncAttributeMaxDynamicSharedMemorySize, FL_SMEM);

    // pre-convert operands to tf32 bits
    concat_kv_kernel<<<6144, 256>>>(x, mem, cmem);
    cvt_kernel<<<2048, 256>>>((const float4*)x,    p_xtf,   524288);
    cvt_kernel<<<1024, 256>>>((const float4*)Wq,   p_wqt,   262144);
    cvt_kernel<<<2048, 256>>>((const float4*)Wkv,  p_wkvt,  524288);
    cvt_kernel<<<1024, 256>>>((const float4*)Wout, p_woutt, 262144);
    cvt_kernel<<<2048, 256>>>((const float4*)mem,  p_memtf, 524288);
    cvt_kernel<<<3072, 256>>>((const float4*)pos,  p_ptf,   786432);
    wtrans_kernel<<<16384, 256>>>(conv_w);

    // q = SCALE * x @ Wq  (tf32 out, pre-scaled for attention)
    mma_gemm_async<128,128,64,32,true><<<dim3(8, 16, 1), 256>>>(
        p_xtf, p_wqt, nullptr, p_q, 1024, 1024, 1024, 1024, SCALE_F, 1, 0,0, 0,0, 0,0);
    // kv = kv_in @ Wkv  (tf32 out)
    mma_gemm_async<128,128,64,32,true><<<dim3(16, 48, 1), 256>>>(
        p_kvin, p_wkvt, nullptr, p_kvout, 1024, 1024, 2048, 2048, 1.0f, 1, 0,0, 0,0, 0,0);

    // fused attention
    flash_kernel<<<dim3(1, 8, 32), 256, FL_SMEM>>>(p_ptf);

    // logits = ctx @ Wout + b_out
    mma_gemm_async<128,128,64,32,false><<<dim3(8, 16, 1), 256>>>(
        p_ctx, p_woutt, b_out, out, 1024, 1024, 1024, 1024, 1.0f, 1, 0,0, 0,0, 0,0);

    // new_mem = x
    copy4_kernel<<<2048, 256>>>((const float4*)x, (float4*)(out + 2097152), 524288);

    // new_cmem part 1: cmem[:, 256:]
    copy4_kernel<<<768, 256>>>((const float4*)(cmem + 262144),  (float4*)(out + 4194304), 196608);
    copy4_kernel<<<768, 256>>>((const float4*)(cmem + 1310720), (float4*)(out + 5242880), 196608);

    // new_cmem part 2: conv as GEMM (M=256, K=4096, N=1024) per batch
    mma_gemm_async<128,128,64,32,false><<<dim3(8, 2, 2), 256>>>(
        p_memtf, p_wt, conv_b, out + 4980736, 4096, 4096, 1024, 1024, 1.0f, 1,
        1048576L, 0L, 0L, 0L, 1048576L, 0L);

    // aux_loss = 0
    aux_kernel<<<1, 1>>>(out + 6291456);
}